// round 6
// baseline (speedup 1.0000x reference)
#include <cuda_runtime.h>

// ---------------- problem constants ----------------
#define DB 2
#define DS 2048
#define DD 512
#define DM 64
#define DT 2112              // DM + DS
#define DN 4224              // DB * DT
#define DH 8
#define DHD 64
#define DWIN 512
#define NSPLIT 8
#define SPLITROWS 528        // DN / NSPLIT
#define NLAY 2
#define LRC 1e-3f
#define WDC 1e-2f
#define EPSC 1e-8f
#define MAXALR 0.01f

typedef unsigned long long u64;

// packed f32x2 helpers (FFMA2 path — only reachable via PTX)
#define DUP2(d, v)   asm("mov.b64 %0, {%1, %1};" : "=l"(d) : "r"(__float_as_uint(v)))
#define FFMA2(c, a, b)   asm("fma.rn.f32x2 %0, %1, %2, %0;" : "+l"(c) : "l"(a), "l"(b))
#define UNPK2(lo, hi, d) do { unsigned _ulo, _uhi; \
    asm("mov.b64 {%0, %1}, %2;" : "=r"(_ulo), "=r"(_uhi) : "l"(d)); \
    lo = __uint_as_float(_ulo); hi = __uint_as_float(_uhi); } while (0)

// ---------------- scratch (device globals; no allocs allowed) ----------------
static __device__ float g_XM[DN * DD];
static __device__ float g_K[DN * DD];
static __device__ float g_V[DN * DD];
static __device__ float g_Q[DN * DD];
static __device__ float g_LR[DN];
static __device__ float g_Z0[DN * DD];
static __device__ float g_X1[DN * DD];
static __device__ float g_Z1[DN * DD];
static __device__ float g_X2[DN * DD];
static __device__ float g_DY2[DN * DD];
static __device__ float g_DZ1[DN * DD];
static __device__ float g_DX1[DN * DD];
static __device__ float g_DZ0[DN * DD];
static __device__ float g_Wn[NLAY * DD * DD];
static __device__ float g_Y1[DN * DD];
static __device__ float g_Y2[DN * DD];
static __device__ float g_AQ[DN * DD];
static __device__ float g_AK[DN * DD];
static __device__ float g_AV[DN * DD];
static __device__ float g_AO[DN * DD];
static __device__ float g_S[DB * DH * DT * DWIN];               // banded scores/probs
static __device__ float g_GP[NLAY * NSPLIT * DD * DD];          // split-K grad partials

__device__ __forceinline__ float sigf(float z) { return 1.0f / (1.0f + __expf(-z)); }
__device__ __forceinline__ float silup(float z) {
    float s = sigf(z);
    return s * (1.0f + z * (1.0f - s));
}

// ================= 64x64x8 double-buffered f32x2 GEMM, 128 threads =================
// per-thread: 8 M-rows (as 4 f32x2 pairs) x 4 N-cols. A pairs read directly from
// smem (packed along M); only 4 B scalars per kk get duplicated.
// ORIENT 0 = NT : C = A @ W^T   (A [M,512], W [N,512], K contiguous in both)
// ORIENT 1 = NN : C = A @ W     (W [512,N])
// ORIENT 2 = TN : C = A^T @ W   (A,W [rows,512]; K = row index over a slice)
// EPI 0: Cz = acc
// EPI 1: Cz = acc ; Cx = A + silu(acc)
// EPI 2: Cx(d_out) = acc, rows mapped to (b, t>=DM)
// EPI 3: Cz = acc + R
template <int ORIENT, int EPI>
__device__ __forceinline__ void gemm_body(
    const float* __restrict__ A, const float* __restrict__ W,
    const float* __restrict__ R, float* __restrict__ Cz, float* __restrict__ Cx,
    int kbase) {
    __shared__ __align__(16) float As[2][8][64];   // As[buf][k][m]
    __shared__ __align__(16) float Bs[2][8][64];   // Bs[buf][k][n]
    const int tid = threadIdx.x;
    const int m0 = blockIdx.x << 6;
    const int n0 = blockIdx.y << 6;
    const int tx = tid & 7;        // -> 8 M rows at tx*8
    const int ty = tid >> 3;       // -> 4 N cols at ty*4  (0..15)

    u64 acc[4][4];                 // [m-pair][n]
#pragma unroll
    for (int i = 0; i < 4; i++)
#pragma unroll
        for (int j = 0; j < 4; j++) acc[i][j] = 0ull;

    // staging indices
    const int arow = tid >> 1, ac4 = (tid & 1) << 2;    // K-contig tiles: 64 rows x 8k
    const int kr = tid >> 4, kc4 = (tid & 15) << 2;     // K-major tiles: 8 rows x 64

    const int NK = (ORIENT == 2 ? SPLITROWS / 8 : DD / 8);

    float4 sa, sb;
    // ---- prologue load (kb = 0)
    {
        const int k0 = kbase;
        if (ORIENT == 2) {
            sa = *(const float4*)&A[(k0 + kr) * DD + m0 + kc4];
            sb = *(const float4*)&W[(k0 + kr) * DD + n0 + kc4];
        } else {
            sa = *(const float4*)&A[(m0 + arow) * DD + k0 + ac4];
            if (ORIENT == 0) sb = *(const float4*)&W[(n0 + arow) * DD + k0 + ac4];
            else             sb = *(const float4*)&W[(k0 + kr) * DD + n0 + kc4];
        }
    }
    // ---- stage buf 0
    {
        if (ORIENT == 2) {
            *(float4*)&As[0][kr][kc4] = sa;
            *(float4*)&Bs[0][kr][kc4] = sb;
        } else {
            As[0][ac4 + 0][arow] = sa.x; As[0][ac4 + 1][arow] = sa.y;
            As[0][ac4 + 2][arow] = sa.z; As[0][ac4 + 3][arow] = sa.w;
            if (ORIENT == 0) {
                Bs[0][ac4 + 0][arow] = sb.x; Bs[0][ac4 + 1][arow] = sb.y;
                Bs[0][ac4 + 2][arow] = sb.z; Bs[0][ac4 + 3][arow] = sb.w;
            } else {
                *(float4*)&Bs[0][kr][kc4] = sb;
            }
        }
    }
    __syncthreads();

    for (int kb = 0; kb < NK; kb++) {
        const int buf = kb & 1;
        if (kb + 1 < NK) {
            const int k0 = kbase + ((kb + 1) << 3);
            if (ORIENT == 2) {
                sa = *(const float4*)&A[(k0 + kr) * DD + m0 + kc4];
                sb = *(const float4*)&W[(k0 + kr) * DD + n0 + kc4];
            } else {
                sa = *(const float4*)&A[(m0 + arow) * DD + k0 + ac4];
                if (ORIENT == 0) sb = *(const float4*)&W[(n0 + arow) * DD + k0 + ac4];
                else             sb = *(const float4*)&W[(k0 + kr) * DD + n0 + kc4];
            }
        }
#pragma unroll
        for (int kk = 0; kk < 8; kk++) {
            ulonglong2 apA = *(const ulonglong2*)&As[buf][kk][tx << 3];       // m pairs 0,1
            ulonglong2 apB = *(const ulonglong2*)&As[buf][kk][(tx << 3) + 4]; // m pairs 2,3
            float4 bv = *(const float4*)&Bs[buf][kk][ty << 2];
            u64 bd0, bd1, bd2, bd3;
            DUP2(bd0, bv.x); DUP2(bd1, bv.y); DUP2(bd2, bv.z); DUP2(bd3, bv.w);
            FFMA2(acc[0][0], apA.x, bd0); FFMA2(acc[0][1], apA.x, bd1);
            FFMA2(acc[0][2], apA.x, bd2); FFMA2(acc[0][3], apA.x, bd3);
            FFMA2(acc[1][0], apA.y, bd0); FFMA2(acc[1][1], apA.y, bd1);
            FFMA2(acc[1][2], apA.y, bd2); FFMA2(acc[1][3], apA.y, bd3);
            FFMA2(acc[2][0], apB.x, bd0); FFMA2(acc[2][1], apB.x, bd1);
            FFMA2(acc[2][2], apB.x, bd2); FFMA2(acc[2][3], apB.x, bd3);
            FFMA2(acc[3][0], apB.y, bd0); FFMA2(acc[3][1], apB.y, bd1);
            FFMA2(acc[3][2], apB.y, bd2); FFMA2(acc[3][3], apB.y, bd3);
        }
        if (kb + 1 < NK) {
            const int nb = buf ^ 1;
            if (ORIENT == 2) {
                *(float4*)&As[nb][kr][kc4] = sa;
                *(float4*)&Bs[nb][kr][kc4] = sb;
            } else {
                As[nb][ac4 + 0][arow] = sa.x; As[nb][ac4 + 1][arow] = sa.y;
                As[nb][ac4 + 2][arow] = sa.z; As[nb][ac4 + 3][arow] = sa.w;
                if (ORIENT == 0) {
                    Bs[nb][ac4 + 0][arow] = sb.x; Bs[nb][ac4 + 1][arow] = sb.y;
                    Bs[nb][ac4 + 2][arow] = sb.z; Bs[nb][ac4 + 3][arow] = sb.w;
                } else {
                    *(float4*)&Bs[nb][kr][kc4] = sb;
                }
            }
        }
        __syncthreads();
    }

    // ---- epilogue: 8 rows (4 pairs), 4 contiguous cols -> one float4 per row
    const int col = n0 + (ty << 2);
#pragma unroll
    for (int i = 0; i < 4; i++) {
        float4 zlo, zhi;
        UNPK2(zlo.x, zhi.x, acc[i][0]);
        UNPK2(zlo.y, zhi.y, acc[i][1]);
        UNPK2(zlo.z, zhi.z, acc[i][2]);
        UNPK2(zlo.w, zhi.w, acc[i][3]);
#pragma unroll
        for (int half = 0; half < 2; half++) {
            const int row = m0 + (tx << 3) + (i << 1) + half;
            float4 z = half ? zhi : zlo;
            if (EPI == 0) {
                *(float4*)&Cz[row * DD + col] = z;
            } else if (EPI == 1) {
                *(float4*)&Cz[row * DD + col] = z;
                float4 a = *(const float4*)&A[row * DD + col];
                float4 o;
                o.x = a.x + z.x * sigf(z.x); o.y = a.y + z.y * sigf(z.y);
                o.z = a.z + z.z * sigf(z.z); o.w = a.w + z.w * sigf(z.w);
                *(float4*)&Cx[row * DD + col] = o;
            } else if (EPI == 3) {
                float4 r = *(const float4*)&R[row * DD + col];
                z.x += r.x; z.y += r.y; z.z += r.z; z.w += r.w;
                *(float4*)&Cz[row * DD + col] = z;
            } else {   // EPI 2: drop meta rows, write d_out
                const int bb = row / DT, t = row - bb * DT;
                if (t >= DM) *(float4*)&Cx[(bb * DS + (t - DM)) * DD + col] = z;
            }
        }
    }
}

template <int ORIENT, int EPI>
__global__ void __launch_bounds__(128, 4) gemm_k(
    const float* __restrict__ A, const float* __restrict__ W,
    const float* __restrict__ R, float* __restrict__ Cz, float* __restrict__ Cx) {
    if (ORIENT == 2) {
        const int sp = blockIdx.z;
        gemm_body<2, EPI>(A, W, R, Cz + sp * DD * DD, Cx, sp * SPLITROWS);
    } else {
        gemm_body<ORIENT, EPI>(A, W, R, Cz, Cx, 0);
    }
}

// batched NT projections: 3 weights, same A, z selects
__global__ void __launch_bounds__(128, 4) gemm_nt3_k(
    const float* __restrict__ A,
    const float* __restrict__ W0, const float* __restrict__ W1, const float* __restrict__ W2,
    float* __restrict__ C0, float* __restrict__ C1, float* __restrict__ C2) {
    const float* W = (blockIdx.z == 0) ? W0 : (blockIdx.z == 1 ? W1 : W2);
    float* C = (blockIdx.z == 0) ? C0 : (blockIdx.z == 1 ? C1 : C2);
    gemm_body<0, 0>(A, W, nullptr, C, nullptr, 0);
}

// ---------------- build xm = concat(meta, x) ----------------
__global__ void build_xm_k(const float* __restrict__ x, const float* __restrict__ meta,
                           float* __restrict__ XM) {
    int idx = blockIdx.x * blockDim.x + threadIdx.x;   // float4 index
    if (idx >= DN * DD / 4) return;
    int e = idx << 2;
    int n = e / DD, d = e - n * DD;
    int b = n / DT, t = n - b * DT;
    float4 v;
    if (t < DM) v = *(const float4*)&meta[t * DD + d];
    else        v = *(const float4*)&x[(b * DS + (t - DM)) * DD + d];
    *(float4*)&XM[e] = v;
}

// ---------------- adaptive lr: sigmoid(xm @ w_lr^T) * MAXALR ----------------
__global__ void lr_proj_k(const float* __restrict__ XM, const float* __restrict__ wlr,
                          float* __restrict__ out) {
    int warp = (blockIdx.x * blockDim.x + threadIdx.x) >> 5;
    int lane = threadIdx.x & 31;
    if (warp >= DN) return;
    const float* xr = XM + warp * DD;
    float s = 0.0f;
#pragma unroll
    for (int i = 0; i < DD / 32; i++) s = fmaf(xr[lane + i * 32], wlr[lane + i * 32], s);
#pragma unroll
    for (int o = 16; o > 0; o >>= 1) s += __shfl_xor_sync(0xffffffffu, s, o);
    if (lane == 0) out[warp] = MAXALR * sigf(s);
}

// ---------------- head gradient + layer1 activation backward (fused) ----------------
__global__ void grad_head_k(const float* __restrict__ X2, const float* __restrict__ Vv,
                            const float* __restrict__ Z1, const float* __restrict__ LRv,
                            float* __restrict__ DY2, float* __restrict__ DZ1) {
    int i = blockIdx.x * blockDim.x + threadIdx.x;
    if (i >= DN * DD) return;
    int n = i >> 9;
    float c = (2.0f / (float)DD) * LRv[n];
    float d2 = c * (X2[i] - Vv[i]);
    DY2[i] = d2;
    DZ1[i] = d2 * silup(Z1[i]);
}

__global__ void bwd_act0_k(const float* __restrict__ DX1, const float* __restrict__ Z0,
                           float* __restrict__ DZ0) {
    int i = blockIdx.x * blockDim.x + threadIdx.x;
    if (i >= DN * DD) return;
    DZ0[i] = DX1[i] * silup(Z0[i]);
}

// ---------------- reduce split-K partials + AdamW first step ----------------
__global__ void adamw_k(const float* __restrict__ W, float* __restrict__ Wn) {
    int idx = blockIdx.x * blockDim.x + threadIdx.x;
    if (idx >= NLAY * DD * DD) return;
    int l = idx / (DD * DD);
    int e = idx - l * (DD * DD);
    const float* gp = g_GP + l * NSPLIT * DD * DD;
    float g = 0.0f;
#pragma unroll
    for (int s = 0; s < NSPLIT; s++) g += gp[s * DD * DD + e];
    g *= (1.0f / 16.0f);
    float w = W[idx];
    Wn[idx] = w * (1.0f - LRC * WDC) - LRC * g / (fabsf(g) + EPSC);
}

#define FMA4x4(a, bb) do { \
    acc[0][0] = fmaf(a.x, bb.x, acc[0][0]); acc[0][1] = fmaf(a.x, bb.y, acc[0][1]); \
    acc[0][2] = fmaf(a.x, bb.z, acc[0][2]); acc[0][3] = fmaf(a.x, bb.w, acc[0][3]); \
    acc[1][0] = fmaf(a.y, bb.x, acc[1][0]); acc[1][1] = fmaf(a.y, bb.y, acc[1][1]); \
    acc[1][2] = fmaf(a.y, bb.z, acc[1][2]); acc[1][3] = fmaf(a.y, bb.w, acc[1][3]); \
    acc[2][0] = fmaf(a.z, bb.x, acc[2][0]); acc[2][1] = fmaf(a.z, bb.y, acc[2][1]); \
    acc[2][2] = fmaf(a.z, bb.z, acc[2][2]); acc[2][3] = fmaf(a.z, bb.w, acc[2][3]); \
    acc[3][0] = fmaf(a.w, bb.x, acc[3][0]); acc[3][1] = fmaf(a.w, bb.y, acc[3][1]); \
    acc[3][2] = fmaf(a.w, bb.z, acc[3][2]); acc[3][3] = fmaf(a.w, bb.w, acc[3][3]); \
} while (0)

// ---------------- attention: banded scores ----------------
__global__ void __launch_bounds__(256, 2) attn_scores_k(
    const float* __restrict__ AQ, const float* __restrict__ AK, float* __restrict__ Sb) {
    __shared__ __align__(16) float Qs[64][68];   // Qs[c][q]
    __shared__ __align__(16) float Ks[64][68];   // Ks[c][k]
    const int q0 = blockIdx.x << 6;
    const int h = blockIdx.y, b = blockIdx.z;
    const int tid = threadIdx.x;
    const int tx = tid & 15, ty = tid >> 4;
#pragma unroll
    for (int i = 0; i < 4; i++) {
        int idx = tid + (i << 8);                 // float4 index 0..1023
        int r = idx >> 4, c4 = (idx & 15) << 2;
        float4 v = *(const float4*)&AQ[(b * DT + q0 + r) * DD + h * DHD + c4];
        Qs[c4 + 0][r] = v.x; Qs[c4 + 1][r] = v.y; Qs[c4 + 2][r] = v.z; Qs[c4 + 3][r] = v.w;
    }
    __syncthreads();
    int kLo = q0 - (DWIN - 1);
    if (kLo < 0) kLo = 0;
    kLo &= ~63;
    for (int k0 = kLo; k0 <= q0 + 63; k0 += 64) {
#pragma unroll
        for (int i = 0; i < 4; i++) {
            int idx = tid + (i << 8);
            int r = idx >> 4, c4 = (idx & 15) << 2;
            int k = k0 + r;
            float4 v = make_float4(0.f, 0.f, 0.f, 0.f);
            if (k < DT) v = *(const float4*)&AK[(b * DT + k) * DD + h * DHD + c4];
            Ks[c4 + 0][r] = v.x; Ks[c4 + 1][r] = v.y; Ks[c4 + 2][r] = v.z; Ks[c4 + 3][r] = v.w;
        }
        __syncthreads();
        float acc[4][4] = {};
#pragma unroll 16
        for (int cc = 0; cc < 64; cc++) {
            float4 a = *(const float4*)&Qs[cc][tx << 2];
            float4 bb = *(const float4*)&Ks[cc][ty << 2];
            FMA4x4(a, bb);
        }
#pragma unroll
        for (int i = 0; i < 4; i++)
#pragma unroll
            for (int j = 0; j < 4; j++) {
                int q = q0 + (tx << 2) + i;
                int k = k0 + (ty << 2) + j;
                if (k <= q && q - k < DWIN)
                    Sb[((b * DH + h) * DT + q) * DWIN + (k - q + DWIN - 1)] = acc[i][j] * 0.125f;
            }
        __syncthreads();
    }
}

// ---------------- attention: softmax over band (warp per row) ----------------
__global__ void attn_softmax_k(float* __restrict__ Sb) {
    int gw = (blockIdx.x * blockDim.x + threadIdx.x) >> 5;
    int lane = threadIdx.x & 31;
    if (gw >= DB * DH * DT) return;
    int q = gw % DT;
    int wlo = DWIN - 1 - q;
    if (wlo < 0) wlo = 0;
    float* row = Sb + gw * DWIN;
    float v[16];
    float m = -1e30f;
#pragma unroll
    for (int i = 0; i < 16; i++) {
        int w = lane + i * 32;
        v[i] = (w >= wlo) ? row[w] : -1e30f;
        m = fmaxf(m, v[i]);
    }
#pragma unroll
    for (int o = 16; o > 0; o >>= 1) m = fmaxf(m, __shfl_xor_sync(0xffffffffu, m, o));
    float sum = 0.0f;
#pragma unroll
    for (int i = 0; i < 16; i++) {
        int w = lane + i * 32;
        v[i] = (w >= wlo) ? __expf(v[i] - m) : 0.0f;
        sum += v[i];
    }
#pragma unroll
    for (int o = 16; o > 0; o >>= 1) sum += __shfl_xor_sync(0xffffffffu, sum, o);
    float inv = 1.0f / sum;
#pragma unroll
    for (int i = 0; i < 16; i++) {
        int w = lane + i * 32;
        if (w >= wlo) row[w] = v[i] * inv;
    }
}

// ---------------- attention: P @ V ----------------
__global__ void __launch_bounds__(256, 2) attn_pv_k(
    const float* __restrict__ Sb, const float* __restrict__ AV, float* __restrict__ AO) {
    __shared__ __align__(16) float Ps[64][68];   // Ps[k][q]
    __shared__ __align__(16) float Vs[64][68];   // Vs[k][c]
    const int q0 = blockIdx.x << 6;
    const int h = blockIdx.y, b = blockIdx.z;
    const int tid = threadIdx.x;
    const int tx = tid & 15, ty = tid >> 4;
    float acc[4][4] = {};
    int kLo = q0 - (DWIN - 1);
    if (kLo < 0) kLo = 0;
    kLo &= ~63;
    for (int k0 = kLo; k0 <= q0 + 63; k0 += 64) {
#pragma unroll
        for (int i = 0; i < 4; i++) {
            int idx = tid + (i << 8);
            int r = idx >> 4, c4 = (idx & 15) << 2;
            int k = k0 + r;
            float4 v = make_float4(0.f, 0.f, 0.f, 0.f);
            if (k < DT) v = *(const float4*)&AV[(b * DT + k) * DD + h * DHD + c4];
            *(float4*)&Vs[r][c4] = v;
        }
#pragma unroll
        for (int i = 0; i < 16; i++) {
            int lin = tid + (i << 8);              // 0..4095
            int qi = lin >> 6, kj = lin & 63;
            int q = q0 + qi, k = k0 + kj;
            float p = 0.0f;
            if (k <= q && q - k < DWIN)
                p = Sb[((b * DH + h) * DT + q) * DWIN + (k - q + DWIN - 1)];
            Ps[kj][qi] = p;
        }
        __syncthreads();
#pragma unroll 16
        for (int kk = 0; kk < 64; kk++) {
            float4 a = *(const float4*)&Ps[kk][tx << 2];
            float4 bb = *(const float4*)&Vs[kk][ty << 2];
            FMA4x4(a, bb);
        }
        __syncthreads();
    }
#pragma unroll
    for (int i = 0; i < 4; i++)
#pragma unroll
        for (int j = 0; j < 4; j++)
            AO[(b * DT + q0 + (tx << 2) + i) * DD + h * DHD + (ty << 2) + j] = acc[i][j];
}

// ---------------- host ----------------
extern "C" void kernel_launch(void* const* d_in, const int* in_sizes, int n_in,
                              void* d_out, int out_size) {
    const float* x      = (const float*)d_in[0];
    const float* meta   = (const float*)d_in[1];
    const float* lmm_w  = (const float*)d_in[2];
    const float* w_q    = (const float*)d_in[3];
    const float* w_k    = (const float*)d_in[4];
    const float* w_v    = (const float*)d_in[5];
    const float* w_lr   = (const float*)d_in[6];
    const float* swa_wq = (const float*)d_in[7];
    const float* swa_wk = (const float*)d_in[8];
    const float* swa_wv = (const float*)d_in[9];
    const float* swa_wo = (const float*)d_in[10];
    float* out = (float*)d_out;

    float *XM, *K, *V, *Q, *LR, *Z0, *X1, *Z1, *X2, *DY2, *DZ1, *DX1, *DZ0;
    float *Wn, *Y1, *Y2, *AQ, *AK, *AV, *AO, *Sb, *GP;
    cudaGetSymbolAddress((void**)&XM, g_XM);
    cudaGetSymbolAddress((void**)&K, g_K);
    cudaGetSymbolAddress((void**)&V, g_V);
    cudaGetSymbolAddress((void**)&Q, g_Q);
    cudaGetSymbolAddress((void**)&LR, g_LR);
    cudaGetSymbolAddress((void**)&Z0, g_Z0);
    cudaGetSymbolAddress((void**)&X1, g_X1);
    cudaGetSymbolAddress((void**)&Z1, g_Z1);
    cudaGetSymbolAddress((void**)&X2, g_X2);
    cudaGetSymbolAddress((void**)&DY2, g_DY2);
    cudaGetSymbolAddress((void**)&DZ1, g_DZ1);
    cudaGetSymbolAddress((void**)&DX1, g_DX1);
    cudaGetSymbolAddress((void**)&DZ0, g_DZ0);
    cudaGetSymbolAddress((void**)&Wn, g_Wn);
    cudaGetSymbolAddress((void**)&Y1, g_Y1);
    cudaGetSymbolAddress((void**)&Y2, g_Y2);
    cudaGetSymbolAddress((void**)&AQ, g_AQ);
    cudaGetSymbolAddress((void**)&AK, g_AK);
    cudaGetSymbolAddress((void**)&AV, g_AV);
    cudaGetSymbolAddress((void**)&AO, g_AO);
    cudaGetSymbolAddress((void**)&Sb, g_S);
    cudaGetSymbolAddress((void**)&GP, g_GP);

    const dim3 gG(DN / 64, DD / 64);            // 66 x 8 = 528 CTAs (single wave @4/SM)
    const dim3 gG3(DN / 64, DD / 64, 3);        // batched projections
    const dim3 gTN(DD / 64, DD / 64, NSPLIT);   // 8 x 8 x 8 = 512 CTAs
    const dim3 gAT(DT / 64, DH, DB);            // 33 x 8 x 2
    const int EW = (DN * DD + 255) / 256;

    // 1. concat meta + x
    build_xm_k<<<(DN * DD / 4 + 255) / 256, 256>>>(x, meta, XM);
    // 2. projections (batched: K, V, Q in one launch)
    gemm_nt3_k<<<gG3, 128>>>(XM, w_k, w_v, w_q, K, V, Q);
    lr_proj_k<<<(DN * 32 + 255) / 256, 256>>>(XM, w_lr, LR);
    // 3. LMM forward on keys (save z for backward)
    gemm_k<0, 1><<<gG, 128>>>(K, lmm_w, nullptr, Z0, X1);
    gemm_k<0, 1><<<gG, 128>>>(X1, lmm_w + DD * DD, nullptr, Z1, X2);
    // 4. backward
    grad_head_k<<<EW, 256>>>(X2, V, Z1, LR, DY2, DZ1);
    gemm_k<2, 0><<<gTN, 128>>>(DZ1, X1, nullptr, GP + NSPLIT * DD * DD, nullptr); // dW1
    gemm_k<1, 3><<<gG, 128>>>(DZ1, lmm_w + DD * DD, DY2, DX1, nullptr);           // dx1
    bwd_act0_k<<<EW, 256>>>(DX1, Z0, DZ0);
    gemm_k<2, 0><<<gTN, 128>>>(DZ0, K, nullptr, GP, nullptr);                     // dW0
    // 5. AdamW first step
    adamw_k<<<(NLAY * DD * DD + 255) / 256, 256>>>(lmm_w, Wn);
    // 6. retrieval with updated weights (Z0/Z1 reused as scratch)
    gemm_k<0, 1><<<gG, 128>>>(Q, Wn, nullptr, Z0, Y1);
    gemm_k<0, 1><<<gG, 128>>>(Y1, Wn + DD * DD, nullptr, Z1, Y2);
    // 7. sliding-window attention (batched QKV projection)
    gemm_nt3_k<<<gG3, 128>>>(Y2, swa_wq, swa_wk, swa_wv, AQ, AK, AV);
    attn_scores_k<<<gAT, 256>>>(AQ, AK, Sb);
    attn_softmax_k<<<(DB * DH * DT * 32 + 255) / 256, 256>>>(Sb);
    attn_pv_k<<<gAT, 256>>>(Sb, AV, AO);
    // 8. output projection, dropping meta rows
    gemm_k<0, 2><<<gG, 128>>>(AO, swa_wo, nullptr, nullptr, out);
}

// round 8
// speedup vs baseline: 2.3608x; 2.3608x over previous
#include <cuda_runtime.h>
#include <cuda_bf16.h>
#include <cstdint>

// ---------------- problem constants ----------------
#define DB 2
#define DS 2048
#define DD 512
#define DM 64
#define DT 2112              // DM + DS
#define DN 4224              // DB * DT
#define DH 8
#define DHD 64
#define DWIN 512
#define NSPLIT 11
#define SPLITROWS 384        // DN / NSPLIT = 384 (6 chunks of 64)
#define NLAY 2
#define LRC 1e-3f
#define WDC 1e-2f
#define EPSC 1e-8f
#define MAXALR 0.01f

// warp-mma tile constants
#define ROWB 144             // bytes per smem tile row (64 bf16 = 128B + 16B pad)
#define TILEB (128 * ROWB)   // 18432 B per tile
#define WM_SMEM (4 * TILEB)  // Ah, Al, Bh, Bl = 73728 B

// ---------------- scratch (device globals; no allocs allowed) ----------------
static __device__ float g_XM[DN * DD];
static __device__ float g_K[DN * DD];
static __device__ float g_V[DN * DD];
static __device__ float g_Q[DN * DD];
static __device__ float g_LR[DN];
static __device__ float g_Z0[DN * DD];
static __device__ float g_X1[DN * DD];
static __device__ float g_Z1[DN * DD];
static __device__ float g_X2[DN * DD];
static __device__ float g_DY2[DN * DD];
static __device__ float g_DZ1[DN * DD];
static __device__ float g_DX1[DN * DD];
static __device__ float g_DZ0[DN * DD];
static __device__ float g_Wn[NLAY * DD * DD];
static __device__ float g_W1t[DD * DD];
static __device__ float g_Y1[DN * DD];
static __device__ float g_Y2[DN * DD];
static __device__ float g_AQ[DN * DD];
static __device__ float g_AK[DN * DD];
static __device__ float g_AV[DN * DD];
static __device__ float g_AO[DN * DD];
static __device__ float g_S[DB * DH * DT * DWIN];               // banded scores/probs
static __device__ float g_GP[NLAY * NSPLIT * DD * DD];          // split-K grad partials

__device__ __forceinline__ float sigf(float z) { return 1.0f / (1.0f + __expf(-z)); }
__device__ __forceinline__ float silup(float z) {
    float s = sigf(z);
    return s * (1.0f + z * (1.0f - s));
}

// ================= warp-mma helpers (sm_80+ baseline PTX, no 'a' features) ======
__device__ __forceinline__ uint32_t smem_u32(const void* p) {
    uint32_t a;
    asm("{ .reg .u64 t; cvta.to.shared.u64 t, %1; cvt.u32.u64 %0, t; }" : "=r"(a) : "l"(p));
    return a;
}
__device__ __forceinline__ void mma16816(float* c, const uint32_t* a, const uint32_t* b) {
    asm volatile(
        "mma.sync.aligned.m16n8k16.row.col.f32.bf16.bf16.f32 "
        "{%0,%1,%2,%3}, {%4,%5,%6,%7}, {%8,%9}, {%0,%1,%2,%3};"
        : "+f"(c[0]), "+f"(c[1]), "+f"(c[2]), "+f"(c[3])
        : "r"(a[0]), "r"(a[1]), "r"(a[2]), "r"(a[3]), "r"(b[0]), "r"(b[1]));
}
__device__ __forceinline__ void ldsm4(uint32_t* r, uint32_t addr) {
    asm volatile("ldmatrix.sync.aligned.m8n8.x4.shared.b16 {%0,%1,%2,%3}, [%4];"
                 : "=r"(r[0]), "=r"(r[1]), "=r"(r[2]), "=r"(r[3]) : "r"(addr));
}
__device__ __forceinline__ void ldsm2(uint32_t* r, uint32_t addr) {
    asm volatile("ldmatrix.sync.aligned.m8n8.x2.shared.b16 {%0,%1}, [%2];"
                 : "=r"(r[0]), "=r"(r[1]) : "r"(addr));
}
// fp32 pair -> bf16x2 hi + bf16x2 lo (split-bf16)
__device__ __forceinline__ void cvt_hl(float a, float b, uint32_t& h, uint32_t& l) {
    __nv_bfloat162 th, tl;
    th.x = __float2bfloat16(a);
    th.y = __float2bfloat16(b);
    tl.x = __float2bfloat16(a - __bfloat162float(th.x));
    tl.y = __float2bfloat16(b - __bfloat162float(th.y));
    h = *reinterpret_cast<uint32_t*>(&th);
    l = *reinterpret_cast<uint32_t*>(&tl);
}

// ---- staging: fp32 K-contig [row][k] source -> bf16 hi/lo tiles (rows x 64k, pad 144B)
__device__ __forceinline__ void stage_nt(const float* __restrict__ src, int row0, int k0,
                                         char* th, char* tl, int tid) {
#pragma unroll
    for (int it = 0; it < 8; it++) {
        int idx = tid + (it << 8);            // 0..2047 float4s
        int m = idx >> 4;                     // 16 float4 per row
        int kq = (idx & 15) << 2;             // 0..60
        float4 v = *(const float4*)&src[(row0 + m) * DD + k0 + kq];
        uint32_t h0, l0, h1, l1;
        cvt_hl(v.x, v.y, h0, l0);
        cvt_hl(v.z, v.w, h1, l1);
        uint32_t off = m * ROWB + (kq << 1);  // 8B aligned
        *(uint2*)(th + off) = make_uint2(h0, h1);
        *(uint2*)(tl + off) = make_uint2(h0 = l0, l1);   // (h0 reused as tmp)
    }
}
// ---- staging transposed: tile(row=i, k) = src[(kb+k)*DD + col0 + i]
__device__ __forceinline__ void stage_tn(const float* __restrict__ src, int col0, int kb,
                                         char* th, char* tl, int tid) {
    const int i = tid & 127;
    const int half = tid >> 7;                // 0,1
#pragma unroll
    for (int it = 0; it < 16; it++) {
        int k = (it << 2) + (half << 1);      // even 0..62
        float v0 = src[(kb + k) * DD + col0 + i];
        float v1 = src[(kb + k + 1) * DD + col0 + i];
        uint32_t h, l;
        cvt_hl(v0, v1, h, l);
        uint32_t off = i * ROWB + (k << 1);
        *(uint32_t*)(th + off) = h;
        *(uint32_t*)(tl + off) = l;
    }
}

// ================= 128x128 warp-mma GEMM body =================
// MODE 0 = NT: C[M,N] = A[M,512] @ W[N,512]^T   (8 chunks of 64)
// MODE 1 = TN: C[i,j] = sum_n A[n,i] W[n,j] over split z (6 chunks of 64)
// EPI 0: Cz = z ; 1: Cz = z, Cx = A + silu(z) ; 2: d_out drop-meta ; 3: Cz = z + R
template <int MODE, int EPI>
__device__ void wm_body(const float* __restrict__ A, const float* __restrict__ W,
                        const float* __restrict__ R, float* __restrict__ Cz,
                        float* __restrict__ Cx) {
    extern __shared__ char sm[];
    char* tAh = sm;
    char* tAl = sm + TILEB;
    char* tBh = sm + 2 * TILEB;
    char* tBl = sm + 3 * TILEB;
    const uint32_t sb = smem_u32(sm);

    const int tid = threadIdx.x;
    const int warp = tid >> 5, lane = tid & 31;
    const int wm = warp >> 2, wn = warp & 3;       // 2 x 4 warp grid
    const int m0 = blockIdx.x << 7;
    const int n0 = blockIdx.y << 7;
    const int kb0 = (MODE == 1) ? blockIdx.z * SPLITROWS : 0;
    const int NCH = (MODE == 1) ? (SPLITROWS / 64) : (DD / 64);
    float* Czp = (MODE == 1) ? (Cz + blockIdx.z * DD * DD) : Cz;

    float acc[4][4][4];
#pragma unroll
    for (int mf = 0; mf < 4; mf++)
#pragma unroll
        for (int nf = 0; nf < 4; nf++)
#pragma unroll
            for (int e = 0; e < 4; e++) acc[mf][nf][e] = 0.0f;

    // ldmatrix lane addressing
    const int ar = (lane & 7) + ((lane >> 3) & 1) * 8;   // row add within frag
    const int acol = (lane >> 4) << 3;                   // 0 or 8
    const int br = lane & 7;
    const int bcol = ((lane >> 3) & 1) << 3;             // 0 or 8 (lanes>=16 ignored)
    const uint32_t aBase = sb + (wm * 64 + ar) * ROWB + acol * 2;
    const uint32_t bBase = sb + 2 * TILEB + (wn * 32 + br) * ROWB + bcol * 2;

    for (int c = 0; c < NCH; c++) {
        const int k0 = kb0 + (c << 6);
        if (MODE == 0) {
            stage_nt(A, m0, k0, tAh, tAl, tid);
            stage_nt(W, n0, k0, tBh, tBl, tid);
        } else {
            stage_tn(A, m0, k0, tAh, tAl, tid);
            stage_tn(W, n0, k0, tBh, tBl, tid);
        }
        __syncthreads();
#pragma unroll
        for (int ks = 0; ks < 4; ks++) {
            const uint32_t kOff = (uint32_t)(ks << 5);   // 16 bf16 = 32B
            uint32_t ah[4][4], al[4][4], bh[4][2], bl[4][2];
#pragma unroll
            for (int mf = 0; mf < 4; mf++) {
                ldsm4(ah[mf], aBase + mf * (16 * ROWB) + kOff);
                ldsm4(al[mf], aBase + TILEB + mf * (16 * ROWB) + kOff);
            }
#pragma unroll
            for (int nf = 0; nf < 4; nf++) {
                ldsm2(bh[nf], bBase + nf * (8 * ROWB) + kOff);
                ldsm2(bl[nf], bBase + TILEB + nf * (8 * ROWB) + kOff);
            }
#pragma unroll
            for (int mf = 0; mf < 4; mf++)
#pragma unroll
                for (int nf = 0; nf < 4; nf++) {
                    mma16816(acc[mf][nf], ah[mf], bh[nf]);
                    mma16816(acc[mf][nf], ah[mf], bl[nf]);
                    mma16816(acc[mf][nf], al[mf], bh[nf]);
                }
        }
        __syncthreads();
    }

    // ---- epilogue: c-frag (row=lane/4, col=2*(lane%4)); rows r and r+8
    const int erow = (lane >> 2);
    const int ecol = (lane & 3) << 1;
#pragma unroll
    for (int mf = 0; mf < 4; mf++)
#pragma unroll
        for (int nf = 0; nf < 4; nf++) {
            const int colg = n0 + wn * 32 + nf * 8 + ecol;
#pragma unroll
            for (int h = 0; h < 2; h++) {
                const int rowg = m0 + wm * 64 + mf * 16 + erow + h * 8;
                float zx = acc[mf][nf][2 * h];
                float zy = acc[mf][nf][2 * h + 1];
                if (EPI == 0) {
                    *(float2*)&Czp[rowg * DD + colg] = make_float2(zx, zy);
                } else if (EPI == 1) {
                    *(float2*)&Czp[rowg * DD + colg] = make_float2(zx, zy);
                    float2 a = *(const float2*)&A[rowg * DD + colg];
                    *(float2*)&Cx[rowg * DD + colg] =
                        make_float2(a.x + zx * sigf(zx), a.y + zy * sigf(zy));
                } else if (EPI == 3) {
                    float2 r = *(const float2*)&R[rowg * DD + colg];
                    *(float2*)&Czp[rowg * DD + colg] = make_float2(zx + r.x, zy + r.y);
                } else {   // EPI 2: drop meta rows -> d_out
                    const int bb = rowg / DT, t = rowg - bb * DT;
                    if (t >= DM)
                        *(float2*)&Cx[(bb * DS + (t - DM)) * DD + colg] = make_float2(zx, zy);
                }
            }
        }
}

template <int MODE, int EPI>
__global__ void __launch_bounds__(256, 1) wm_gemm_k(
    const float* __restrict__ A, const float* __restrict__ W,
    const float* __restrict__ R, float* __restrict__ Cz, float* __restrict__ Cx) {
    wm_body<MODE, EPI>(A, W, R, Cz, Cx);
}

__global__ void __launch_bounds__(256, 1) wm_nt3_k(
    const float* __restrict__ A,
    const float* __restrict__ W0, const float* __restrict__ W1, const float* __restrict__ W2,
    float* __restrict__ C0, float* __restrict__ C1, float* __restrict__ C2) {
    const float* W = (blockIdx.z == 0) ? W0 : (blockIdx.z == 1 ? W1 : W2);
    float* C = (blockIdx.z == 0) ? C0 : (blockIdx.z == 1 ? C1 : C2);
    wm_body<0, 0>(A, W, nullptr, C, nullptr);
}

// ---------------- 512x512 transpose (for NN -> NT) ----------------
__global__ void transpose_k(const float* __restrict__ in, float* __restrict__ outp) {
    __shared__ float t[32][33];
    int x = blockIdx.x * 32 + threadIdx.x;
    int y = blockIdx.y * 32 + threadIdx.y;
#pragma unroll
    for (int j = 0; j < 32; j += 8) t[threadIdx.y + j][threadIdx.x] = in[(y + j) * DD + x];
    __syncthreads();
    x = blockIdx.y * 32 + threadIdx.x;
    y = blockIdx.x * 32 + threadIdx.y;
#pragma unroll
    for (int j = 0; j < 32; j += 8) outp[(y + j) * DD + x] = t[threadIdx.x][threadIdx.y + j];
}

// ---------------- build xm = concat(meta, x) ----------------
__global__ void build_xm_k(const float* __restrict__ x, const float* __restrict__ meta,
                           float* __restrict__ XM) {
    int idx = blockIdx.x * blockDim.x + threadIdx.x;
    if (idx >= DN * DD / 4) return;
    int e = idx << 2;
    int n = e / DD, d = e - n * DD;
    int b = n / DT, t = n - b * DT;
    float4 v;
    if (t < DM) v = *(const float4*)&meta[t * DD + d];
    else        v = *(const float4*)&x[(b * DS + (t - DM)) * DD + d];
    *(float4*)&XM[e] = v;
}

// ---------------- adaptive lr ----------------
__global__ void lr_proj_k(const float* __restrict__ XM, const float* __restrict__ wlr,
                          float* __restrict__ out) {
    int warp = (blockIdx.x * blockDim.x + threadIdx.x) >> 5;
    int lane = threadIdx.x & 31;
    if (warp >= DN) return;
    const float* xr = XM + warp * DD;
    float s = 0.0f;
#pragma unroll
    for (int i = 0; i < DD / 32; i++) s = fmaf(xr[lane + i * 32], wlr[lane + i * 32], s);
#pragma unroll
    for (int o = 16; o > 0; o >>= 1) s += __shfl_xor_sync(0xffffffffu, s, o);
    if (lane == 0) out[warp] = MAXALR * sigf(s);
}

// ---------------- head gradient + layer1 act backward ----------------
__global__ void grad_head_k(const float* __restrict__ X2, const float* __restrict__ Vv,
                            const float* __restrict__ Z1, const float* __restrict__ LRv,
                            float* __restrict__ DY2, float* __restrict__ DZ1) {
    int i = blockIdx.x * blockDim.x + threadIdx.x;
    if (i >= DN * DD) return;
    int n = i >> 9;
    float c = (2.0f / (float)DD) * LRv[n];
    float d2 = c * (X2[i] - Vv[i]);
    DY2[i] = d2;
    DZ1[i] = d2 * silup(Z1[i]);
}

__global__ void bwd_act0_k(const float* __restrict__ DX1, const float* __restrict__ Z0,
                           float* __restrict__ DZ0) {
    int i = blockIdx.x * blockDim.x + threadIdx.x;
    if (i >= DN * DD) return;
    DZ0[i] = DX1[i] * silup(Z0[i]);
}

// ---------------- reduce split-K partials + AdamW ----------------
__global__ void adamw_k(const float* __restrict__ W, float* __restrict__ Wn) {
    int idx = blockIdx.x * blockDim.x + threadIdx.x;
    if (idx >= NLAY * DD * DD) return;
    int l = idx / (DD * DD);
    int e = idx - l * (DD * DD);
    const float* gp = g_GP + l * NSPLIT * DD * DD;
    float g = 0.0f;
#pragma unroll
    for (int s = 0; s < NSPLIT; s++) g += gp[s * DD * DD + e];
    g *= (1.0f / 16.0f);
    float w = W[idx];
    Wn[idx] = w * (1.0f - LRC * WDC) - LRC * g / (fabsf(g) + EPSC);
}

#define FMA4x4(a, bb) do { \
    acc[0][0] = fmaf(a.x, bb.x, acc[0][0]); acc[0][1] = fmaf(a.x, bb.y, acc[0][1]); \
    acc[0][2] = fmaf(a.x, bb.z, acc[0][2]); acc[0][3] = fmaf(a.x, bb.w, acc[0][3]); \
    acc[1][0] = fmaf(a.y, bb.x, acc[1][0]); acc[1][1] = fmaf(a.y, bb.y, acc[1][1]); \
    acc[1][2] = fmaf(a.y, bb.z, acc[1][2]); acc[1][3] = fmaf(a.y, bb.w, acc[1][3]); \
    acc[2][0] = fmaf(a.z, bb.x, acc[2][0]); acc[2][1] = fmaf(a.z, bb.y, acc[2][1]); \
    acc[2][2] = fmaf(a.z, bb.z, acc[2][2]); acc[2][3] = fmaf(a.z, bb.w, acc[2][3]); \
    acc[3][0] = fmaf(a.w, bb.x, acc[3][0]); acc[3][1] = fmaf(a.w, bb.y, acc[3][1]); \
    acc[3][2] = fmaf(a.w, bb.z, acc[3][2]); acc[3][3] = fmaf(a.w, bb.w, acc[3][3]); \
} while (0)

// ---------------- attention: banded scores ----------------
__global__ void __launch_bounds__(256, 2) attn_scores_k(
    const float* __restrict__ AQ, const float* __restrict__ AK, float* __restrict__ Sb) {
    __shared__ __align__(16) float Qs[64][68];
    __shared__ __align__(16) float Ks[64][68];
    const int q0 = blockIdx.x << 6;
    const int h = blockIdx.y, b = blockIdx.z;
    const int tid = threadIdx.x;
    const int tx = tid & 15, ty = tid >> 4;
#pragma unroll
    for (int i = 0; i < 4; i++) {
        int idx = tid + (i << 8);
        int r = idx >> 4, c4 = (idx & 15) << 2;
        float4 v = *(const float4*)&AQ[(b * DT + q0 + r) * DD + h * DHD + c4];
        Qs[c4 + 0][r] = v.x; Qs[c4 + 1][r] = v.y; Qs[c4 + 2][r] = v.z; Qs[c4 + 3][r] = v.w;
    }
    __syncthreads();
    int kLo = q0 - (DWIN - 1);
    if (kLo < 0) kLo = 0;
    kLo &= ~63;
    for (int k0 = kLo; k0 <= q0 + 63; k0 += 64) {
#pragma unroll
        for (int i = 0; i < 4; i++) {
            int idx = tid + (i << 8);
            int r = idx >> 4, c4 = (idx & 15) << 2;
            int k = k0 + r;
            float4 v = make_float4(0.f, 0.f, 0.f, 0.f);
            if (k < DT) v = *(const float4*)&AK[(b * DT + k) * DD + h * DHD + c4];
            Ks[c4 + 0][r] = v.x; Ks[c4 + 1][r] = v.y; Ks[c4 + 2][r] = v.z; Ks[c4 + 3][r] = v.w;
        }
        __syncthreads();
        float acc[4][4] = {};
#pragma unroll 16
        for (int cc = 0; cc < 64; cc++) {
            float4 a = *(const float4*)&Qs[cc][tx << 2];
            float4 bb = *(const float4*)&Ks[cc][ty << 2];
            FMA4x4(a, bb);
        }
#pragma unroll
        for (int i = 0; i < 4; i++)
#pragma unroll
            for (int j = 0; j < 4; j++) {
                int q = q0 + (tx << 2) + i;
                int k = k0 + (ty << 2) + j;
                if (k <= q && q - k < DWIN)
                    Sb[((b * DH + h) * DT + q) * DWIN + (k - q + DWIN - 1)] = acc[i][j] * 0.125f;
            }
        __syncthreads();
    }
}

// ---------------- attention: softmax over band ----------------
__global__ void attn_softmax_k(float* __restrict__ Sb) {
    int gw = (blockIdx.x * blockDim.x + threadIdx.x) >> 5;
    int lane = threadIdx.x & 31;
    if (gw >= DB * DH * DT) return;
    int q = gw % DT;
    int wlo = DWIN - 1 - q;
    if (wlo < 0) wlo = 0;
    float* row = Sb + gw * DWIN;
    float v[16];
    float m = -1e30f;
#pragma unroll
    for (int i = 0; i < 16; i++) {
        int w = lane + i * 32;
        v[i] = (w >= wlo) ? row[w] : -1e30f;
        m = fmaxf(m, v[i]);
    }
#pragma unroll
    for (int o = 16; o > 0; o >>= 1) m = fmaxf(m, __shfl_xor_sync(0xffffffffu, m, o));
    float sum = 0.0f;
#pragma unroll
    for (int i = 0; i < 16; i++) {
        int w = lane + i * 32;
        v[i] = (w >= wlo) ? __expf(v[i] - m) : 0.0f;
        sum += v[i];
    }
#pragma unroll
    for (int o = 16; o > 0; o >>= 1) sum += __shfl_xor_sync(0xffffffffu, sum, o);
    float inv = 1.0f / sum;
#pragma unroll
    for (int i = 0; i < 16; i++) {
        int w = lane + i * 32;
        if (w >= wlo) row[w] = v[i] * inv;
    }
}

// ---------------- attention: P @ V ----------------
__global__ void __launch_bounds__(256, 2) attn_pv_k(
    const float* __restrict__ Sb, const float* __restrict__ AV, float* __restrict__ AO) {
    __shared__ __align__(16) float Ps[64][68];
    __shared__ __align__(16) float Vs[64][68];
    const int q0 = blockIdx.x << 6;
    const int h = blockIdx.y, b = blockIdx.z;
    const int tid = threadIdx.x;
    const int tx = tid & 15, ty = tid >> 4;
    float acc[4][4] = {};
    int kLo = q0 - (DWIN - 1);
    if (kLo < 0) kLo = 0;
    kLo &= ~63;
    for (int k0 = kLo; k0 <= q0 + 63; k0 += 64) {
#pragma unroll
        for (int i = 0; i < 4; i++) {
            int idx = tid + (i << 8);
            int r = idx >> 4, c4 = (idx & 15) << 2;
            int k = k0 + r;
            float4 v = make_float4(0.f, 0.f, 0.f, 0.f);
            if (k < DT) v = *(const float4*)&AV[(b * DT + k) * DD + h * DHD + c4];
            *(float4*)&Vs[r][c4] = v;
        }
#pragma unroll
        for (int i = 0; i < 16; i++) {
            int lin = tid + (i << 8);
            int qi = lin >> 6, kj = lin & 63;
            int q = q0 + qi, k = k0 + kj;
            float p = 0.0f;
            if (k <= q && q - k < DWIN)
                p = Sb[((b * DH + h) * DT + q) * DWIN + (k - q + DWIN - 1)];
            Ps[kj][qi] = p;
        }
        __syncthreads();
#pragma unroll 16
        for (int kk = 0; kk < 64; kk++) {
            float4 a = *(const float4*)&Ps[kk][tx << 2];
            float4 bb = *(const float4*)&Vs[kk][ty << 2];
            FMA4x4(a, bb);
        }
        __syncthreads();
    }
#pragma unroll
    for (int i = 0; i < 4; i++)
#pragma unroll
        for (int j = 0; j < 4; j++)
            AO[(b * DT + q0 + (tx << 2) + i) * DD + h * DHD + (ty << 2) + j] = acc[i][j];
}

// ---------------- host ----------------
extern "C" void kernel_launch(void* const* d_in, const int* in_sizes, int n_in,
                              void* d_out, int out_size) {
    const float* x      = (const float*)d_in[0];
    const float* meta   = (const float*)d_in[1];
    const float* lmm_w  = (const float*)d_in[2];
    const float* w_q    = (const float*)d_in[3];
    const float* w_k    = (const float*)d_in[4];
    const float* w_v    = (const float*)d_in[5];
    const float* w_lr   = (const float*)d_in[6];
    const float* swa_wq = (const float*)d_in[7];
    const float* swa_wk = (const float*)d_in[8];
    const float* swa_wv = (const float*)d_in[9];
    const float* swa_wo = (const float*)d_in[10];
    float* out = (float*)d_out;

    float *XM, *K, *V, *Q, *LR, *Z0, *X1, *Z1, *X2, *DY2, *DZ1, *DX1, *DZ0;
    float *Wn, *W1t, *Y1, *Y2, *AQ, *AK, *AV, *AO, *Sb, *GP;
    cudaGetSymbolAddress((void**)&XM, g_XM);
    cudaGetSymbolAddress((void**)&K, g_K);
    cudaGetSymbolAddress((void**)&V, g_V);
    cudaGetSymbolAddress((void**)&Q, g_Q);
    cudaGetSymbolAddress((void**)&LR, g_LR);
    cudaGetSymbolAddress((void**)&Z0, g_Z0);
    cudaGetSymbolAddress((void**)&X1, g_X1);
    cudaGetSymbolAddress((void**)&Z1, g_Z1);
    cudaGetSymbolAddress((void**)&X2, g_X2);
    cudaGetSymbolAddress((void**)&DY2, g_DY2);
    cudaGetSymbolAddress((void**)&DZ1, g_DZ1);
    cudaGetSymbolAddress((void**)&DX1, g_DX1);
    cudaGetSymbolAddress((void**)&DZ0, g_DZ0);
    cudaGetSymbolAddress((void**)&Wn, g_Wn);
    cudaGetSymbolAddress((void**)&W1t, g_W1t);
    cudaGetSymbolAddress((void**)&Y1, g_Y1);
    cudaGetSymbolAddress((void**)&Y2, g_Y2);
    cudaGetSymbolAddress((void**)&AQ, g_AQ);
    cudaGetSymbolAddress((void**)&AK, g_AK);
    cudaGetSymbolAddress((void**)&AV, g_AV);
    cudaGetSymbolAddress((void**)&AO, g_AO);
    cudaGetSymbolAddress((void**)&Sb, g_S);
    cudaGetSymbolAddress((void**)&GP, g_GP);

    cudaFuncSetAttribute(wm_nt3_k, cudaFuncAttributeMaxDynamicSharedMemorySize, WM_SMEM);
    cudaFuncSetAttribute(wm_gemm_k<0, 1>, cudaFuncAttributeMaxDynamicSharedMemorySize, WM_SMEM);
    cudaFuncSetAttribute(wm_gemm_k<0, 2>, cudaFuncAttributeMaxDynamicSharedMemorySize, WM_SMEM);
    cudaFuncSetAttribute(wm_gemm_k<0, 3>, cudaFuncAttributeMaxDynamicSharedMemorySize, WM_SMEM);
    cudaFuncSetAttribute(wm_gemm_k<1, 0>, cudaFuncAttributeMaxDynamicSharedMemorySize, WM_SMEM);

    const dim3 gG(DN / 128, DD / 128);          // 33 x 4
    const dim3 gG3(DN / 128, DD / 128, 3);      // batched projections
    const dim3 gTN(DD / 128, DD / 128, NSPLIT); // 4 x 4 x 11
    const dim3 gAT(DT / 64, DH, DB);            // 33 x 8 x 2
    const int EW = (DN * DD + 255) / 256;

    // 1. concat meta + x ; transpose W1 for the NN gemm
    build_xm_k<<<(DN * DD / 4 + 255) / 256, 256>>>(x, meta, XM);
    transpose_k<<<dim3(16, 16), dim3(32, 8)>>>(lmm_w + DD * DD, W1t);
    // 2. projections (K, V, Q batched)
    wm_nt3_k<<<gG3, 256, WM_SMEM>>>(XM, w_k, w_v, w_q, K, V, Q);
    lr_proj_k<<<(DN * 32 + 255) / 256, 256>>>(XM, w_lr, LR);
    // 3. LMM forward on keys
    wm_gemm_k<0, 1><<<gG, 256, WM_SMEM>>>(K, lmm_w, nullptr, Z0, X1);
    wm_gemm_k<0, 1><<<gG, 256, WM_SMEM>>>(X1, lmm_w + DD * DD, nullptr, Z1, X2);
    // 4. backward
    grad_head_k<<<EW, 256>>>(X2, V, Z1, LR, DY2, DZ1);
    wm_gemm_k<1, 0><<<gTN, 256, WM_SMEM>>>(DZ1, X1, nullptr, GP + NSPLIT * DD * DD, nullptr); // dW1
    wm_gemm_k<0, 3><<<gG, 256, WM_SMEM>>>(DZ1, W1t, DY2, DX1, nullptr);                       // dx1
    bwd_act0_k<<<EW, 256>>>(DX1, Z0, DZ0);
    wm_gemm_k<1, 0><<<gTN, 256, WM_SMEM>>>(DZ0, K, nullptr, GP, nullptr);                     // dW0
    // 5. AdamW first step
    adamw_k<<<(NLAY * DD * DD + 255) / 256, 256>>>(lmm_w, Wn);
    // 6. retrieval with updated weights
    wm_gemm_k<0, 1><<<gG, 256, WM_SMEM>>>(Q, Wn, nullptr, Z0, Y1);
    wm_gemm_k<0, 1><<<gG, 256, WM_SMEM>>>(Y1, Wn + DD * DD, nullptr, Z1, Y2);
    // 7. sliding-window attention
    wm_nt3_k<<<gG3, 256, WM_SMEM>>>(Y2, swa_wq, swa_wk, swa_wv, AQ, AK, AV);
    attn_scores_k<<<gAT, 256>>>(AQ, AK, Sb);
    attn_softmax_k<<<(DB * DH * DT * 32 + 255) / 256, 256>>>(Sb);
    attn_pv_k<<<gAT, 256>>>(Sb, AV, AO);
    // 8. output projection, dropping meta rows
    wm_gemm_k<0, 2><<<gG, 256, WM_SMEM>>>(AO, swa_wo, nullptr, nullptr, out);
}